// round 1
// baseline (speedup 1.0000x reference)
#include <cuda_runtime.h>
#include <math.h>

// GMM_64003602645506 — GMM E-step NLL on GB300 (sm_103a)
// Strategy: per-component homogeneous packed quadratic form in smem,
// online softmax over components, warp-level work stealing.

#define D        32
#define DH       33                       // homogeneous dim [x, 1]
#define K        64
#define NPACK    ((DH*(DH+1))/2)          // 561
#define PSTRIDE  564                      // pad to multiple of 4 (16B align)
#define LOG_2PI  1.8378770664093453f
#define TPB      512

__device__ float  g_P[K * PSTRIDE];       // packed homogeneous forms
__device__ float  g_lw[K];                // log softmax(log_weights)
__device__ double g_acc;                  // sum of per-sample log-likelihood
__device__ int    g_counter;              // work-stealing counter

// ---------------------------------------------------------------------------
// Kernel 0: normalize log_weights (log-softmax), zero accumulators. 32 threads.
// ---------------------------------------------------------------------------
__global__ void lw_zero_kernel(const float* __restrict__ log_weights) {
    int t = threadIdx.x;                  // 0..31
    float v0 = log_weights[t];
    float v1 = log_weights[t + 32];
    float mx = fmaxf(v0, v1);
    #pragma unroll
    for (int o = 16; o; o >>= 1) mx = fmaxf(mx, __shfl_xor_sync(0xffffffffu, mx, o));
    float s = expf(v0 - mx) + expf(v1 - mx);
    #pragma unroll
    for (int o = 16; o; o >>= 1) s += __shfl_xor_sync(0xffffffffu, s, o);
    float lse = mx + logf(s);
    g_lw[t]      = v0 - lse;
    g_lw[t + 32] = v1 - lse;
    if (t == 0) { g_acc = 0.0; g_counter = 0; }
}

// ---------------------------------------------------------------------------
// Kernel 1: per-component precompute. 64 blocks x 32 threads.
//   A = L^-1 (forward substitution, one column per thread)
//   M = A^T A ; b = M mu ; c = mu^T b ; hld = sum log diag(L)
//   Pack homogeneous Q (off-diag doubled) into g_P[k].
// ---------------------------------------------------------------------------
__global__ void precompute_kernel(const float* __restrict__ means,
                                  const float* __restrict__ scale_tril) {
    int k = blockIdx.x;
    int t = threadIdx.x;                  // 0..31
    __shared__ float Ls[D][D];
    __shared__ float As[D][D + 1];
    __shared__ float mu[D];
    __shared__ float u[D];
    __shared__ float b[D];

    for (int i = t; i < D * D; i += 32)
        Ls[i / D][i % D] = scale_tril[k * D * D + i];
    mu[t] = means[k * D + t];
    __syncwarp();

    // half-logdet (butterfly -> all lanes)
    float hld = logf(Ls[t][t]);
    #pragma unroll
    for (int o = 16; o; o >>= 1) hld += __shfl_xor_sync(0xffffffffu, hld, o);

    // invert L: thread t owns column t of A
    float a[D];
    #pragma unroll
    for (int i = 0; i < D; i++) a[i] = 0.0f;
    a[t] = 1.0f / Ls[t][t];
    for (int i = t + 1; i < D; i++) {
        float s = 0.0f;
        for (int j = t; j < i; j++) s += Ls[i][j] * a[j];
        a[i] = -s / Ls[i][i];
    }
    #pragma unroll
    for (int i = 0; i < D; i++) As[i][t] = a[i];
    __syncwarp();

    // u = A mu (row t)
    {
        float s = 0.0f;
        for (int j = 0; j <= t; j++) s += As[t][j] * mu[j];
        u[t] = s;
    }
    __syncwarp();
    // b = A^T u (column t)
    {
        float s = 0.0f;
        for (int r = t; r < D; r++) s += As[r][t] * u[r];
        b[t] = s;
    }
    __syncwarp();
    // c = mu . b (butterfly -> all lanes)
    float c = b[t] * mu[t];
    #pragma unroll
    for (int o = 16; o; o >>= 1) c += __shfl_xor_sync(0xffffffffu, c, o);

    // pack homogeneous Q
    float* P = &g_P[k * PSTRIDE];
    for (int idx = t; idx < PSTRIDE; idx += 32) {
        float val = 0.0f;
        if (idx < NPACK) {
            int i = 0, rem = idx;
            while (rem >= DH - i) { rem -= (DH - i); i++; }
            int j = i + rem;
            if (j < D) {
                float s = 0.0f;
                for (int r = j; r < D; r++) s += As[r][i] * As[r][j];
                val = (i == j) ? s : 2.0f * s;
            } else if (i < D) {           // linear term (j == 32)
                val = -2.0f * b[i];
            } else {                      // constant (i == j == 32)
                val = c + (float)D * LOG_2PI + 2.0f * hld;
            }
        }
        P[idx] = val;
    }
}

// ---------------------------------------------------------------------------
// Kernel 2: main. Persistent CTAs (one per SM), warp-level work stealing.
// Each thread owns one sample per stolen batch; loops k over 64 components,
// evaluates packed quadratic form from smem (broadcast), online softmax.
// ---------------------------------------------------------------------------
__global__ void __launch_bounds__(TPB) gmm_main(const float* __restrict__ X, int N) {
    extern __shared__ float sm[];
    float* sP  = sm;                      // K*PSTRIDE floats
    float* sLW = sm + K * PSTRIDE;        // K floats

    for (int i = threadIdx.x; i < K * PSTRIDE; i += TPB) sP[i] = g_P[i];
    if (threadIdx.x < K) sLW[threadIdx.x] = g_lw[threadIdx.x];
    __syncthreads();

    const int lane = threadIdx.x & 31;
    float accf = 0.0f;

    for (;;) {
        int base;
        if (lane == 0) base = atomicAdd(&g_counter, 32);
        base = __shfl_sync(0xffffffffu, base, 0);
        if (base >= N) break;
        int n = base + lane;

        float y[DH];
        if (n < N) {
            const float4* Xv = reinterpret_cast<const float4*>(X) + (size_t)n * 8;
            #pragma unroll
            for (int v = 0; v < 8; v++) {
                float4 f = Xv[v];
                y[4*v+0] = f.x; y[4*v+1] = f.y; y[4*v+2] = f.z; y[4*v+3] = f.w;
            }
        } else {
            #pragma unroll
            for (int i = 0; i < D; i++) y[i] = 0.0f;
        }
        y[D] = 1.0f;

        float m = -1e30f, S = 0.0f, T = 0.0f;
        #pragma unroll 1
        for (int k = 0; k < K; k++) {
            const float* Pk = sP + k * PSTRIDE;
            float q = 0.0f;
            int p = 0;
            #pragma unroll
            for (int i = 0; i < DH; i++) {
                float t0 = 0.0f;
                #pragma unroll
                for (int j = i; j < DH; j++) { t0 = fmaf(Pk[p], y[j], t0); p++; }
                q = fmaf(y[i], t0, q);
            }
            float logp = -0.5f * q;       // includes D*log2pi + 2*hld folded in
            float g = logp + sLW[k];
            float m2 = fmaxf(m, g);
            float sa = __expf(m - m2);
            float e  = __expf(g - m2);
            S = fmaf(S, sa, e);
            T = fmaf(T, sa, e * logp);
            m = m2;
        }
        if (n < N) accf += T / S;         // sum_k resp * logp for this sample
    }

    // warp reduce, one atomic per warp
    #pragma unroll
    for (int o = 16; o; o >>= 1) accf += __shfl_xor_sync(0xffffffffu, accf, o);
    if (lane == 0) atomicAdd(&g_acc, (double)accf);
}

// ---------------------------------------------------------------------------
// Kernel 3: finalize scalar output.
// ---------------------------------------------------------------------------
__global__ void finalize_kernel(float* __restrict__ out, int N) {
    out[0] = (float)(-g_acc / (double)N);
}

// ---------------------------------------------------------------------------
extern "C" void kernel_launch(void* const* d_in, const int* in_sizes, int n_in,
                              void* d_out, int out_size) {
    const float* X           = (const float*)d_in[0];
    const float* means       = (const float*)d_in[1];
    const float* scale_tril  = (const float*)d_in[2];
    const float* log_weights = (const float*)d_in[3];
    float* out = (float*)d_out;

    int N = in_sizes[0] / D;

    size_t smem = (size_t)(K * PSTRIDE + K) * sizeof(float);
    cudaFuncSetAttribute(gmm_main, cudaFuncAttributeMaxDynamicSharedMemorySize,
                         (int)smem);

    int nsm = 148;
    cudaDeviceGetAttribute(&nsm, cudaDevAttrMultiProcessorCount, 0);

    lw_zero_kernel<<<1, 32>>>(log_weights);
    precompute_kernel<<<K, 32>>>(means, scale_tril);
    gmm_main<<<nsm, TPB, smem>>>(X, N);
    finalize_kernel<<<1, 1>>>(out, N);
}

// round 3
// speedup vs baseline: 2.4307x; 2.4307x over previous
#include <cuda_runtime.h>
#include <math.h>
#include <stdint.h>

// GMM_64003602645506 — mma.sync (HMMA tf32) formulation for sm_103 (no 'a').
// logp(n,k) = -0.5*<Q_k, phi(x_n)> + c2_k, phi = {x_i*x_j (i<=j), x_i, pad}.
// Per 128-sample tile: D[128x64] = Phi[128x576] @ Q^T via m16n8k8 tf32 mma.
// Q in smem in fragment order (conflict-free LDS.128); Phi built into smem
// fragment-order double buffers by builder warps (XOR lane swizzle).

#define D        32
#define K        64
#define NQUAD    528
#define NF       576
#define TILE_M   128
#define TPB      256
#define LOG_2PI  1.8378770664093453f

// smem byte offsets
#define SQ_OFF    0
#define SQ_WORDS  36864                     // 2h*72s*2v*32t*4e
#define SQ_BYTES  (SQ_WORDS * 4)            // 147456
#define SA_OFF    SQ_BYTES
#define SA_BUF_F4 2048                      // float4 per buffer (8mt*8sl*32)
#define SA_BYTES  (2 * SA_BUF_F4 * 16)      // 65536
#define SLW_OFF   (SA_OFF + SA_BYTES)       // 212992
#define SC2_OFF   (SLW_OFF + 256)
#define STILE_OFF (SC2_OFF + 256)
#define SMEM_TOTAL (STILE_OFF + 16)

__device__ float  g_B[K * NF];
__device__ float  g_c2[K];
__device__ float  g_lw[K];
__device__ double g_acc;
__device__ int    g_counter;

// ---------------------------------------------------------------------------
__device__ __forceinline__ float tf32rn(float f) {
    uint32_t r;
    asm("cvt.rn.tf32.f32 %0, %1;" : "=r"(r) : "f"(f));
    return __uint_as_float(r);
}

// feature f of phi(x); folds to a single FMUL / mov when f is compile-time.
__device__ __forceinline__ float feat(const float* x, int f) {
    if (f >= NQUAD + D) return 0.0f;
    if (f >= NQUAD)     return x[f - NQUAD];
    float r = 0.0f;
    #pragma unroll
    for (int i = 0; i < D; i++) {
        const int start = i * D - (i * (i - 1)) / 2;
        const int cnt   = D - i;
        if (f >= start && f < start + cnt) r = x[i] * x[f - start + i];
    }
    return r;
}

// m16n8k8 tf32 mma: c += a * b
__device__ __forceinline__ void mma8(float* c, float4 a, float b0, float b1) {
    asm volatile(
        "mma.sync.aligned.m16n8k8.row.col.f32.tf32.tf32.f32 "
        "{%0,%1,%2,%3}, {%4,%5,%6,%7}, {%8,%9}, {%0,%1,%2,%3};"
        : "+f"(c[0]), "+f"(c[1]), "+f"(c[2]), "+f"(c[3])
        : "r"(__float_as_uint(a.x)), "r"(__float_as_uint(a.y)),
          "r"(__float_as_uint(a.z)), "r"(__float_as_uint(a.w)),
          "r"(__float_as_uint(b0)), "r"(__float_as_uint(b1)));
}

// ---------------------------------------------------------------------------
// Builder: thread owns samples (mt*16+rr, +8); writes A-fragments for chunk C,
// sl in [SH, SH+4). One STS.128 per (sl,q): {x0@f, x1@f, x0@f+4, x1@f+4}.
// ---------------------------------------------------------------------------
template <int C, int SH>
__device__ __forceinline__ void build_chunk(const float* x0, const float* x1,
                                            float4* dst, int mt, int rr) {
    #pragma unroll
    for (int sl2 = 0; sl2 < 4; sl2++) {
        const int sl = SH + sl2;
        #pragma unroll
        for (int q = 0; q < 4; q++) {
            const int f0 = C * 64 + sl * 8 + q;
            float4 v;
            v.x = tf32rn(feat(x0, f0));
            v.y = tf32rn(feat(x1, f0));
            v.z = tf32rn(feat(x0, f0 + 4));
            v.w = tf32rn(feat(x1, f0 + 4));
            dst[(mt * 8 + sl) * 32 + ((rr * 4 + q) ^ (mt & 3))] = v;
        }
    }
}

template <int C>
__device__ __forceinline__ void build_c(int sh, const float* x0, const float* x1,
                                        float4* dst, int mt, int rr) {
    if (sh == 0) build_chunk<C, 0>(x0, x1, dst, mt, rr);
    else         build_chunk<C, 4>(x0, x1, dst, mt, rr);
}

__device__ __forceinline__ void do_build(int cc, int sh, const float* x0,
                                         const float* x1, float4* dst,
                                         int mt, int rr) {
    switch (cc) {
        case 0: build_c<0>(sh, x0, x1, dst, mt, rr); break;
        case 1: build_c<1>(sh, x0, x1, dst, mt, rr); break;
        case 2: build_c<2>(sh, x0, x1, dst, mt, rr); break;
        case 3: build_c<3>(sh, x0, x1, dst, mt, rr); break;
        case 4: build_c<4>(sh, x0, x1, dst, mt, rr); break;
        case 5: build_c<5>(sh, x0, x1, dst, mt, rr); break;
        case 6: build_c<6>(sh, x0, x1, dst, mt, rr); break;
        case 7: build_c<7>(sh, x0, x1, dst, mt, rr); break;
        case 8: build_c<8>(sh, x0, x1, dst, mt, rr); break;
    }
}

// ---------------------------------------------------------------------------
// Kernel 0: log-softmax of log_weights + reset accumulators.
// ---------------------------------------------------------------------------
__global__ void lw_zero_kernel(const float* __restrict__ log_weights) {
    int t = threadIdx.x;
    float v0 = log_weights[t], v1 = log_weights[t + 32];
    float mx = fmaxf(v0, v1);
    #pragma unroll
    for (int o = 16; o; o >>= 1) mx = fmaxf(mx, __shfl_xor_sync(~0u, mx, o));
    float s = expf(v0 - mx) + expf(v1 - mx);
    #pragma unroll
    for (int o = 16; o; o >>= 1) s += __shfl_xor_sync(~0u, s, o);
    float lse = mx + logf(s);
    g_lw[t] = v0 - lse;
    g_lw[t + 32] = v1 - lse;
    if (t == 0) { g_acc = 0.0; g_counter = 0; }
}

// ---------------------------------------------------------------------------
// Kernel 1: per-component precompute -> packed Q (tf32-rounded) + constants.
// ---------------------------------------------------------------------------
__global__ void precompute_kernel(const float* __restrict__ means,
                                  const float* __restrict__ scale_tril) {
    int k = blockIdx.x, t = threadIdx.x;
    __shared__ float Ls[D][D], As[D][D + 1], mu[D], u[D], b[D];

    for (int i = t; i < D * D; i += 32)
        Ls[i / D][i % D] = scale_tril[k * D * D + i];
    mu[t] = means[k * D + t];
    __syncwarp();

    float hld = logf(Ls[t][t]);
    #pragma unroll
    for (int o = 16; o; o >>= 1) hld += __shfl_xor_sync(~0u, hld, o);

    float a[D];
    #pragma unroll
    for (int i = 0; i < D; i++) a[i] = 0.0f;
    a[t] = 1.0f / Ls[t][t];
    for (int i = t + 1; i < D; i++) {
        float s = 0.0f;
        for (int j = t; j < i; j++) s += Ls[i][j] * a[j];
        a[i] = -s / Ls[i][i];
    }
    #pragma unroll
    for (int i = 0; i < D; i++) As[i][t] = a[i];
    __syncwarp();

    { float s = 0.0f; for (int j = 0; j <= t; j++) s += As[t][j] * mu[j]; u[t] = s; }
    __syncwarp();
    { float s = 0.0f; for (int r = t; r < D; r++) s += As[r][t] * u[r]; b[t] = s; }
    __syncwarp();
    float c = b[t] * mu[t];
    #pragma unroll
    for (int o = 16; o; o >>= 1) c += __shfl_xor_sync(~0u, c, o);

    for (int f = t; f < NF; f += 32) {
        float val = 0.0f;
        if (f < NQUAD) {
            int i = 0, rem = f;
            while (rem >= D - i) { rem -= (D - i); i++; }
            int j = i + rem;
            float s = 0.0f;
            for (int r = j; r < D; r++) s += As[r][i] * As[r][j];
            val = (i == j) ? s : 2.0f * s;
        } else if (f < NQUAD + D) {
            val = -2.0f * b[f - NQUAD];
        }
        g_B[k * NF + f] = tf32rn(val);
    }
    if (t == 0) g_c2[k] = -0.5f * (c + (float)D * LOG_2PI) - hld;
}

// ---------------------------------------------------------------------------
// Kernel 2: main persistent kernel. 8 warps: 0-3 MMA, 4-7 builders.
// MMA warp w: samples (w&1)*64..+64 (m-tiles), comps (w>>1)*32..+32.
// ---------------------------------------------------------------------------
__global__ void __launch_bounds__(TPB, 1) gmm_main(const float* __restrict__ X,
                                                   int N, int ntiles) {
    extern __shared__ char smem[];
    const int tid = threadIdx.x;
    const int wid = tid >> 5;
    const int lane = tid & 31;

    float* sLW = (float*)(smem + SLW_OFF);
    float* sC2 = (float*)(smem + SC2_OFF);
    int*   sTile = (int*)(smem + STILE_OFF);

    // --- one-time init: Q into fragment-order smem, constants ---
    if (tid < K) { sLW[tid] = g_lw[tid]; sC2[tid] = g_c2[tid]; }
    for (int idx = tid; idx < SQ_WORDS; idx += TPB) {
        int h  = idx / 18432;
        int r1 = idx - h * 18432;
        int s  = r1 >> 8;
        int r2 = r1 & 255;
        int v  = r2 >> 7;
        int r3 = r2 & 127;
        int t  = r3 >> 2;
        int e  = r3 & 3;
        int nt = v * 2 + (e >> 1);
        int kk = (t & 3) + (e & 1) * 4;
        int comp = h * 32 + nt * 8 + (t >> 2);
        ((float*)(smem + SQ_OFF))[idx] = g_B[comp * NF + s * 8 + kk];
    }
    __syncthreads();

    // builder identity
    const int bt = tid - 128;              // valid for wid>=4
    const int pr = bt & 63;
    const int sh = (bt >> 6) ? 4 : 0;
    const int bmt = pr >> 3, brr = pr & 7;

    // MMA identity
    const int mh = wid & 1, h = wid >> 1;

    const float4* q4 = (const float4*)(smem + SQ_OFF) + h * 4608 + lane;
    float4* a4base = (float4*)(smem + SA_OFF);
    float*  sD = (float*)(smem + SA_OFF);

    float accf = 0.0f;
    float x0[D], x1[D];

    for (;;) {
        if (tid == 0) sTile[0] = atomicAdd(&g_counter, 1);
        __syncthreads();
        const int tile = sTile[0];
        if (tile >= ntiles) break;

        float acc[4][4][4];
        if (wid < 4) {
            #pragma unroll
            for (int a = 0; a < 4; a++)
                #pragma unroll
                for (int b = 0; b < 4; b++)
                    #pragma unroll
                    for (int c = 0; c < 4; c++) acc[a][b][c] = 0.0f;
        } else {
            // load x pair
            int s0 = tile * TILE_M + bmt * 16 + brr;
            int s1 = s0 + 8;
            const float4* xv = (const float4*)X;
            if (s0 < N) {
                #pragma unroll
                for (int v = 0; v < 8; v++) {
                    float4 f4 = xv[(size_t)s0 * 8 + v];
                    x0[4*v] = f4.x; x0[4*v+1] = f4.y; x0[4*v+2] = f4.z; x0[4*v+3] = f4.w;
                }
            } else {
                #pragma unroll
                for (int i = 0; i < D; i++) x0[i] = 0.0f;
            }
            if (s1 < N) {
                #pragma unroll
                for (int v = 0; v < 8; v++) {
                    float4 f4 = xv[(size_t)s1 * 8 + v];
                    x1[4*v] = f4.x; x1[4*v+1] = f4.y; x1[4*v+2] = f4.z; x1[4*v+3] = f4.w;
                }
            } else {
                #pragma unroll
                for (int i = 0; i < D; i++) x1[i] = 0.0f;
            }
            // build chunk 0 into buf 0
            do_build(0, sh, x0, x1, a4base, bmt, brr);
        }
        __syncthreads();

        for (int c = 0; c < 9; c++) {
            if (wid >= 4) {
                if (c < 8)
                    do_build(c + 1, sh, x0, x1, a4base + ((c + 1) & 1) * SA_BUF_F4,
                             bmt, brr);
            } else {
                const float4* a4 = a4base + (c & 1) * SA_BUF_F4;
                #pragma unroll
                for (int sl = 0; sl < 8; sl++) {
                    float4 b0v = q4[(c * 8 + sl) * 64];
                    float4 b1v = q4[(c * 8 + sl) * 64 + 32];
                    #pragma unroll
                    for (int mt4 = 0; mt4 < 4; mt4++) {
                        float4 av = a4[((mh * 4 + mt4) * 8 + sl) * 32 + (lane ^ mt4)];
                        mma8(acc[mt4][0], av, b0v.x, b0v.y);
                        mma8(acc[mt4][1], av, b0v.z, b0v.w);
                        mma8(acc[mt4][2], av, b1v.x, b1v.y);
                        mma8(acc[mt4][3], av, b1v.z, b1v.w);
                    }
                }
            }
            __syncthreads();
        }

        // epilogue: C frags -> sD[128][66]
        if (wid < 4) {
            #pragma unroll
            for (int mt4 = 0; mt4 < 4; mt4++) {
                #pragma unroll
                for (int nt = 0; nt < 4; nt++) {
                    int r0  = mh * 64 + mt4 * 16 + (lane >> 2);
                    int col = h * 32 + nt * 8 + (lane & 3) * 2;
                    *(float2*)&sD[r0 * 66 + col] =
                        make_float2(acc[mt4][nt][0], acc[mt4][nt][1]);
                    *(float2*)&sD[(r0 + 8) * 66 + col] =
                        make_float2(acc[mt4][nt][2], acc[mt4][nt][3]);
                }
            }
        }
        __syncthreads();

        if (tid < TILE_M) {
            int n = tile * TILE_M + tid;
            float lp[K];
            float m = -1e30f;
            #pragma unroll
            for (int k = 0; k < K; k++) {
                lp[k] = fmaf(-0.5f, sD[tid * 66 + k], sC2[k]);
                m = fmaxf(m, lp[k] + sLW[k]);
            }
            float S = 0.0f, T = 0.0f;
            #pragma unroll
            for (int k = 0; k < K; k++) {
                float e = __expf(lp[k] + sLW[k] - m);
                S += e;
                T = fmaf(e, lp[k], T);
            }
            if (n < N) accf += T / S;
        }
        __syncthreads();
    }

    // reduce (only tid<128 hold contributions)
    #pragma unroll
    for (int o = 16; o; o >>= 1) accf += __shfl_xor_sync(~0u, accf, o);
    if (wid < 4 && lane == 0) atomicAdd(&g_acc, (double)accf);
}

// ---------------------------------------------------------------------------
__global__ void finalize_kernel(float* __restrict__ out, int N) {
    out[0] = (float)(-g_acc / (double)N);
}

// ---------------------------------------------------------------------------
extern "C" void kernel_launch(void* const* d_in, const int* in_sizes, int n_in,
                              void* d_out, int out_size) {
    const float* X           = (const float*)d_in[0];
    const float* means       = (const float*)d_in[1];
    const float* scale_tril  = (const float*)d_in[2];
    const float* log_weights = (const float*)d_in[3];
    float* out = (float*)d_out;

    int N = in_sizes[0] / D;
    int ntiles = (N + TILE_M - 1) / TILE_M;

    cudaFuncSetAttribute(gmm_main, cudaFuncAttributeMaxDynamicSharedMemorySize,
                         SMEM_TOTAL);
    int nsm = 148;
    cudaDeviceGetAttribute(&nsm, cudaDevAttrMultiProcessorCount, 0);

    lw_zero_kernel<<<1, 32>>>(log_weights);
    precompute_kernel<<<K, 32>>>(means, scale_tril);
    gmm_main<<<nsm, TPB, SMEM_TOTAL>>>(X, N, ntiles);
    finalize_kernel<<<1, 1>>>(out, N);
}